// round 16
// baseline (speedup 1.0000x reference)
#include <cuda_runtime.h>
#include <cstdint>

#define C_NUM 100000
#define D_NUM 256
#define B_NUM 1024
#define EPSV 1e-12f
#define COPY_CTAS_Y 16           // y [0,16):   128 copy CTAs (leading)
#define GEMM_TILES_Y 782         // y [16,798): GEMM tiles
#define SCAT_CTAS_Y 4            // y [798,802): 32 scatter CTAs (trailing)
#define CHAIN_BLKS 128
#define UPD_BLKS 128             // gated update blocks inside prep
#define WINV_BLKS 3125           // 8 warps each, 4 rows per warp (MLP=8)

__device__ float g_xnorm[B_NUM * D_NUM];   // tf32-rounded normalized x
__device__ float g_xexact[B_NUM * D_NUM];  // exact normalized x
__device__ float g_winv[C_NUM];
__device__ float g_upd_val[B_NUM * D_NUM]; // staged updated rows (indexed by head b)
__device__ int   g_next[B_NUM];
__device__ int   g_head[B_NUM];
__device__ int   g_copy_done;              // copy-CTA completion counter (gemm)
__device__ int   g_prep_cnt;               // xnorm+chain arrival counter (prep)

__device__ __forceinline__ uint32_t smem_u32(const void* p) {
    uint32_t a;
    asm("{ .reg .u64 t; cvta.to.shared.u64 t, %1; cvt.u32.u64 %0, t; }" : "=r"(a) : "l"(p));
    return a;
}
__device__ __forceinline__ unsigned f2tf(float f) {
    unsigned u;
    asm("cvt.rna.tf32.f32 %0, %1;" : "=r"(u) : "f"(f));
    return u;
}
__device__ __forceinline__ void cp16(uint32_t daddr, const void* gptr) {
    asm volatile("cp.async.cg.shared.global [%0], [%1], 16;" :: "r"(daddr), "l"(gptr) : "memory");
}
#define CP_COMMIT() asm volatile("cp.async.commit_group;" ::: "memory")

__device__ __forceinline__ void ldsm4(unsigned r[4], uint32_t addr) {
    asm volatile("ldmatrix.sync.aligned.m8n8.x4.shared.b16 {%0,%1,%2,%3}, [%4];"
                 : "=r"(r[0]), "=r"(r[1]), "=r"(r[2]), "=r"(r[3]) : "r"(addr));
}
__device__ __forceinline__ void mma_tf32(float d[4], const unsigned a[4], const unsigned b[2]) {
    asm volatile(
        "mma.sync.aligned.m16n8k8.row.col.f32.tf32.tf32.f32 "
        "{%0,%1,%2,%3}, {%4,%5,%6,%7}, {%8,%9}, {%0,%1,%2,%3};\n"
        : "+f"(d[0]), "+f"(d[1]), "+f"(d[2]), "+f"(d[3])
        : "r"(a[0]), "r"(a[1]), "r"(a[2]), "r"(a[3]),
          "r"(b[0]), "r"(b[1]));
}
__device__ __forceinline__ uint32_t sw128(uint32_t off) { return off ^ ((off >> 3) & 0x70); }

// ---------------------------------------------------------------------------
// K_PREP fused grid:
//   [0, 1024)        xnorm (arrive on g_prep_cnt)
//   [1024, 1152)     chain (ballot fwd+bwd; arrive; block 1024 resets copy gate)
//   [1152, 1280)     update -> staging (gated on g_prep_cnt == 1152)
//   [1280, 4405)     winv  (4 class rows per warp, MLP=8)
// Update blocks hide under winv's ~16us DRAM-bound shadow.
// ---------------------------------------------------------------------------
__global__ void k_prep(const float* __restrict__ x, const int* __restrict__ tgt,
                       const float4* __restrict__ w4, float* __restrict__ out_t) {
    const int by = blockIdx.x;
    const int t = threadIdx.x;

    if (by < B_NUM) {                    // ---- xnorm row `by` ----
        __shared__ float ws[8];
        float v = x[by * D_NUM + t];
        float ss = v * v;
        #pragma unroll
        for (int o = 16; o; o >>= 1) ss += __shfl_xor_sync(0xffffffffu, ss, o);
        if ((t & 31) == 0) ws[t >> 5] = ss;
        __syncthreads();
        float tot = 0.f;
        #pragma unroll
        for (int i = 0; i < 8; ++i) tot += ws[i];
        float inv = 1.f / fmaxf(sqrtf(tot), EPSV);
        float xn = v * inv;
        g_xexact[by * D_NUM + t] = xn;
        g_xnorm[by * D_NUM + t] = __uint_as_float(f2tf(xn));
        if (t == 0) out_t[by] = (float)tgt[by];
        __threadfence();
        __syncthreads();
        if (t == 0) atomicAdd(&g_prep_cnt, 1);
    } else if (by < B_NUM + CHAIN_BLKS) {   // ---- chain: ballot scans ----
        __shared__ int st[B_NUM];
        if (by == B_NUM && t == 0) g_copy_done = 0;   // reset gemm gate each replay
        #pragma unroll
        for (int k = 0; k < 4; ++k) st[t + k * 256] = tgt[t + k * 256];
        __syncthreads();
        const int lane = t & 31;
        const int i = (by - B_NUM) * 8 + (t >> 5);   // 0..1023, one per warp
        const int me = st[i];
        int prev = -1;
        for (int start = i - 1; start >= 0; start -= 32) {
            int j = start - lane;
            unsigned m = __ballot_sync(0xffffffffu, (j >= 0) && (st[j] == me));
            if (m) { prev = start - (__ffs(m) - 1); break; }
        }
        int nxt = -1;
        for (int start = i + 1; start < B_NUM; start += 32) {
            int j = start + lane;
            unsigned m = __ballot_sync(0xffffffffu, (j < B_NUM) && (st[j] == me));
            if (m) { nxt = start + (__ffs(m) - 1); break; }
        }
        if (lane == 0) {
            g_head[i] = (prev < 0) ? 1 : 0;
            g_next[i] = nxt;
        }
        __threadfence();
        __syncthreads();
        if (t == 0) atomicAdd(&g_prep_cnt, 1);
    } else if (by < B_NUM + CHAIN_BLKS + UPD_BLKS) {  // ---- gated update ----
        __shared__ float ws[8];
        if (t == 0) {
            while (atomicAdd(&g_prep_cnt, 0) < B_NUM + CHAIN_BLKS) { }
        }
        __syncthreads();
        const float* W = (const float*)w4;
        int slot0 = (by - B_NUM - CHAIN_BLKS) * 8;
        for (int s = 0; s < 8; ++s) {
            int b = slot0 + s;
            if (!g_head[b]) continue;        // block-uniform branch
            int y = tgt[b];
            float v = W[(size_t)y * D_NUM + t];   // raw bank row
            int cur = b;
            while (cur >= 0) {
                v = 0.5f * v + 0.5f * g_xexact[cur * D_NUM + t];
                float ss = v * v;
                #pragma unroll
                for (int o = 16; o; o >>= 1) ss += __shfl_xor_sync(0xffffffffu, ss, o);
                __syncthreads();
                if ((t & 31) == 0) ws[t >> 5] = ss;
                __syncthreads();
                float tot = 0.f;
                #pragma unroll
                for (int i = 0; i < 8; ++i) tot += ws[i];
                v *= 1.f / fmaxf(sqrtf(tot), EPSV);
                cur = g_next[cur];
            }
            g_upd_val[(size_t)b * D_NUM + t] = v;   // staged; scattered post-copy
            __syncthreads();
        }
    } else {                             // ---- winv: 4 class rows per warp ----
        int gw = ((by - B_NUM - CHAIN_BLKS - UPD_BLKS) * 8 + (t >> 5)) * 4;
        int lane = t & 31;
        if (gw < C_NUM) {
            float s[4];
            #pragma unroll
            for (int r = 0; r < 4; ++r) {
                const float4* rp = w4 + (size_t)(gw + r) * 64;
                float4 a = rp[lane];
                float4 b = rp[lane + 32];
                s[r] = a.x*a.x + a.y*a.y + a.z*a.z + a.w*a.w
                     + b.x*b.x + b.y*b.y + b.z*b.z + b.w*b.w;
            }
            #pragma unroll
            for (int o = 16; o; o >>= 1) {
                #pragma unroll
                for (int r = 0; r < 4; ++r)
                    s[r] += __shfl_xor_sync(0xffffffffu, s[r], o);
            }
            if (lane == 0) {
                #pragma unroll
                for (int r = 0; r < 4; ++r)
                    g_winv[gw + r] = 1.f / fmaxf(sqrtf(s[r]), EPSV);
            }
        }
    }
}

// ---------------------------------------------------------------------------
// K_GEMM mega-grid:
//   y [0,16)    : copy W -> new_weight (unconditional 4-way unrolled, R10)
//   y [16,798)  : TF32 mma.sync GEMM tiles (R10 core, untouched)
//   y [798,802) : scatter staged updated rows into nw (gated on copy done)
// ---------------------------------------------------------------------------
#define NSTG 3
#define STG_BYTES 32768            // A(16KB) + B(16KB) per stage
#define OFF_TILE 1024
#define SMEM_BYTES (OFF_TILE + NSTG * STG_BYTES)

__global__ __launch_bounds__(256, 2)
void k_gemm(const float* __restrict__ W, float* __restrict__ out,
            float4* __restrict__ nw4, const int* __restrict__ tgt) {
    const int tid = threadIdx.x;
    extern __shared__ char smem[];

    // ---- leading copy CTAs: unconditional 4-way unrolled (R10 exact) ----
    if (blockIdx.y < COPY_CTAS_Y) {
        if (blockIdx.y == 0 && blockIdx.x == 0 && tid == 0) g_prep_cnt = 0;  // reset prep gate
        const float4* src = (const float4*)W;
        const size_t n4 = (size_t)C_NUM * 64;
        const size_t nthr = (size_t)COPY_CTAS_Y * 8 * 256;   // 32768
        size_t base = (size_t)(blockIdx.y * 8 + blockIdx.x) * 256 + tid;
        size_t i = base;
        for (; i + 3 * nthr < n4; i += 4 * nthr) {
            float4 v0 = src[i];
            float4 v1 = src[i + nthr];
            float4 v2 = src[i + 2 * nthr];
            float4 v3 = src[i + 3 * nthr];
            nw4[i] = v0; nw4[i + nthr] = v1;
            nw4[i + 2 * nthr] = v2; nw4[i + 3 * nthr] = v3;
        }
        for (; i < n4; i += nthr) nw4[i] = src[i];
        __threadfence();
        __syncthreads();
        if (tid == 0) atomicAdd(&g_copy_done, 1);
        return;
    }

    // ---- trailing scatter CTAs: staged rows -> nw, after copy done ----
    if (blockIdx.y >= COPY_CTAS_Y + GEMM_TILES_Y) {
        if (tid == 0) {
            while (atomicAdd(&g_copy_done, 0) < COPY_CTAS_Y * 8) { }
        }
        __syncthreads();
        float* nw = (float*)nw4;
        int idx = (blockIdx.y - COPY_CTAS_Y - GEMM_TILES_Y) * 8 + blockIdx.x; // 0..31
        int b0 = idx * 32;
        for (int s = 0; s < 32; s += 4) {
            float v[4]; int hd[4], yy[4];
            #pragma unroll
            for (int u = 0; u < 4; ++u) {
                int b = b0 + s + u;
                hd[u] = g_head[b];
                yy[u] = tgt[b];
                v[u]  = g_upd_val[(size_t)b * D_NUM + tid];
            }
            #pragma unroll
            for (int u = 0; u < 4; ++u)
                if (hd[u]) nw[(size_t)yy[u] * D_NUM + tid] = v[u];
        }
        return;
    }

    const uint32_t sb = smem_u32(smem);
    const int lane = tid & 31, warp = tid >> 5;
    const int b0 = blockIdx.x * 128;                    // batch tile
    const int c0 = (blockIdx.y - COPY_CTAS_Y) * 128;    // class tile
    const int wm = (warp & 1) * 64;
    const int wn = (warp >> 1) * 32;

    float* winv_s = (float*)smem;      // [128] = 30*winv
    if (tid < 128) {
        int c = c0 + tid; if (c >= C_NUM) c = C_NUM - 1;
        winv_s[tid] = 30.0f * g_winv[c];
    }

    const char* Abase = (const char*)g_xnorm + (size_t)b0 * (D_NUM * 4);
    const char* Bbase = (const char*)W;

    auto issue_load = [&](int stage, int chunk) {
        uint32_t abuf = sb + OFF_TILE + stage * STG_BYTES;
        uint32_t bbuf = abuf + 16384;
        #pragma unroll
        for (int i = 0; i < 4; ++i) {
            int slot = tid + i * 256;          // 0..1023
            int r = slot >> 3;
            int sg = (slot & 7) * 16;
            uint32_t so = sw128((uint32_t)(r * 128 + sg));
            cp16(abuf + so, Abase + (size_t)r * 1024 + chunk * 128 + sg);
            int row = c0 + r; if (row >= C_NUM) row = C_NUM - 1;
            cp16(bbuf + so, Bbase + (size_t)row * 1024 + chunk * 128 + sg);
        }
        CP_COMMIT();
    };

    float acc[4][4][4];
    #pragma unroll
    for (int i = 0; i < 4; ++i)
        #pragma unroll
        for (int j = 0; j < 4; ++j)
            #pragma unroll
            for (int r = 0; r < 4; ++r) acc[i][j][r] = 0.f;

    uint32_t a_off[4], b_off[2];
    #pragma unroll
    for (int im = 0; im < 4; ++im)
        a_off[im] = (uint32_t)((wm + im * 16 + (lane & 15)) * 128 + ((lane >> 4) << 4));
    #pragma unroll
    for (int jp = 0; jp < 2; ++jp)
        b_off[jp] = (uint32_t)((wn + jp * 16 + ((lane >> 4) << 3) + (lane & 7)) * 128
                               + (((lane >> 3) & 1) << 4));

    issue_load(0, 0);
    issue_load(1, 1);

    #pragma unroll
    for (int c = 0; c < 8; ++c) {
        if (c < 7) asm volatile("cp.async.wait_group 1;" ::: "memory");
        else       asm volatile("cp.async.wait_group 0;" ::: "memory");
        __syncthreads();
        if (c + 2 < 8) issue_load((c + 2) % NSTG, c + 2);  // stage freed at this barrier

        const uint32_t abuf = sb + OFF_TILE + (c % NSTG) * STG_BYTES;
        const uint32_t bbuf = abuf + 16384;
        #pragma unroll
        for (int ks = 0; ks < 4; ++ks) {
            unsigned af[4][4], bf[2][4];
            #pragma unroll
            for (int im = 0; im < 4; ++im)
                ldsm4(af[im], abuf + sw128(a_off[im] + ks * 32));
            #pragma unroll
            for (int jp = 0; jp < 2; ++jp)
                ldsm4(bf[jp], bbuf + sw128(b_off[jp] + ks * 32));
            #pragma unroll
            for (int im = 0; im < 4; ++im) {
                #pragma unroll
                for (int jp = 0; jp < 2; ++jp) {
                    mma_tf32(acc[im][jp * 2 + 0], af[im], &bf[jp][0]);
                    mma_tf32(acc[im][jp * 2 + 1], af[im], &bf[jp][2]);
                }
            }
        }
    }
    __syncthreads();   // all reads of last stage done before tb reuse

    // epilogue: scale by 30*winv, smem transpose, coalesced float4 stores
    float* tb = (float*)(smem + OFF_TILE);   // [128][132]
    const int g4 = lane >> 2, t4 = lane & 3;
    #pragma unroll
    for (int im = 0; im < 4; ++im) {
        int r = wm + im * 16 + g4;
        #pragma unroll
        for (int jn = 0; jn < 4; ++jn) {
            int col = wn + jn * 8 + t4 * 2;
            float s0 = winv_s[col], s1 = winv_s[col + 1];
            *(float2*)&tb[r * 132 + col] =
                make_float2(acc[im][jn][0] * s0, acc[im][jn][1] * s1);
            *(float2*)&tb[(r + 8) * 132 + col] =
                make_float2(acc[im][jn][2] * s0, acc[im][jn][3] * s1);
        }
    }
    __syncthreads();
    #pragma unroll
    for (int it = 0; it < 16; ++it) {
        int r = warp + it * 8;
        int colb = lane * 4;
        float4 val = *(const float4*)&tb[r * 132 + colb];
        int gc = c0 + colb;
        if (gc < C_NUM)
            *(float4*)&out[(size_t)(b0 + r) * C_NUM + gc] = val;
    }
}

// ---------------------------------------------------------------------------
extern "C" void kernel_launch(void* const* d_in, const int* in_sizes, int n_in,
                              void* d_out, int out_size) {
    const float* x   = (const float*)d_in[0];
    const int*   tgt = (const int*)d_in[1];
    const float* w   = (const float*)d_in[2];
    float* out      = (float*)d_out;
    float* out_pred = out;                                  // [1024][100000]
    float* out_t    = out + (size_t)B_NUM * C_NUM;          // [1024]
    float* out_nw   = out_t + B_NUM;                        // [100000][256]

    static bool attr_set = false;
    if (!attr_set) {
        cudaFuncSetAttribute(k_gemm, cudaFuncAttributeMaxDynamicSharedMemorySize, SMEM_BYTES);
        attr_set = true;
    }

    k_prep<<<B_NUM + CHAIN_BLKS + UPD_BLKS + WINV_BLKS, 256>>>(x, tgt, (const float4*)w, out_t);
    k_gemm<<<dim3(8, COPY_CTAS_Y + GEMM_TILES_Y + SCAT_CTAS_Y), 256, SMEM_BYTES>>>(
        w, out_pred, (float4*)out_nw, tgt);
}

// round 17
// speedup vs baseline: 1.4975x; 1.4975x over previous
#include <cuda_runtime.h>
#include <cstdint>

#define C_NUM 100000
#define D_NUM 256
#define B_NUM 1024
#define EPSV 1e-12f
#define COPY_CTAS_Y 16           // first 16 y-slots * 8 x = 128 copy CTAs
#define GEMM_TILES_Y 782
#define CHAIN_BLKS 128           // 8 warps each -> 1024 warps, one per element
#define WINV_BLKS 6250           // 8 warps each, 2 rows per warp

__device__ float g_xnorm[B_NUM * D_NUM];   // tf32-rounded normalized x
__device__ float g_xexact[B_NUM * D_NUM];  // exact normalized x
__device__ float g_winv[C_NUM];
__device__ int   g_next[B_NUM];
__device__ int   g_head[B_NUM];

__device__ __forceinline__ uint32_t smem_u32(const void* p) {
    uint32_t a;
    asm("{ .reg .u64 t; cvta.to.shared.u64 t, %1; cvt.u32.u64 %0, t; }" : "=r"(a) : "l"(p));
    return a;
}
__device__ __forceinline__ unsigned f2tf(float f) {
    unsigned u;
    asm("cvt.rna.tf32.f32 %0, %1;" : "=r"(u) : "f"(f));
    return u;
}
__device__ __forceinline__ void cp16(uint32_t daddr, const void* gptr) {
    asm volatile("cp.async.cg.shared.global [%0], [%1], 16;" :: "r"(daddr), "l"(gptr) : "memory");
}
#define CP_COMMIT() asm volatile("cp.async.commit_group;" ::: "memory")

__device__ __forceinline__ void ldsm4(unsigned r[4], uint32_t addr) {
    asm volatile("ldmatrix.sync.aligned.m8n8.x4.shared.b16 {%0,%1,%2,%3}, [%4];"
                 : "=r"(r[0]), "=r"(r[1]), "=r"(r[2]), "=r"(r[3]) : "r"(addr));
}
__device__ __forceinline__ void mma_tf32(float d[4], const unsigned a[4], const unsigned b[2]) {
    asm volatile(
        "mma.sync.aligned.m16n8k8.row.col.f32.tf32.tf32.f32 "
        "{%0,%1,%2,%3}, {%4,%5,%6,%7}, {%8,%9}, {%0,%1,%2,%3};\n"
        : "+f"(d[0]), "+f"(d[1]), "+f"(d[2]), "+f"(d[3])
        : "r"(a[0]), "r"(a[1]), "r"(a[2]), "r"(a[3]),
          "r"(b[0]), "r"(b[1]));
}
__device__ __forceinline__ uint32_t sw128(uint32_t off) { return off ^ ((off >> 3) & 0x70); }

// ---------------------------------------------------------------------------
// K_PREP fused grid:
//   [0, 1024)            xnorm (one batch row each)
//   [1024, 1024+128)     chain (warp-ballot fwd+bwd, 1 elem/warp)
//   [1152, 1152+6250)    winv  (2 class rows per warp, MLP=4)
// ---------------------------------------------------------------------------
__global__ void k_prep(const float* __restrict__ x, const int* __restrict__ tgt,
                       const float4* __restrict__ w4, float* __restrict__ out_t) {
    const int by = blockIdx.x;
    const int t = threadIdx.x;

    if (by < B_NUM) {                    // ---- xnorm row `by` ----
        __shared__ float ws[8];
        float v = x[by * D_NUM + t];
        float ss = v * v;
        #pragma unroll
        for (int o = 16; o; o >>= 1) ss += __shfl_xor_sync(0xffffffffu, ss, o);
        if ((t & 31) == 0) ws[t >> 5] = ss;
        __syncthreads();
        float tot = 0.f;
        #pragma unroll
        for (int i = 0; i < 8; ++i) tot += ws[i];
        float inv = 1.f / fmaxf(sqrtf(tot), EPSV);
        float xn = v * inv;
        g_xexact[by * D_NUM + t] = xn;
        g_xnorm[by * D_NUM + t] = __uint_as_float(f2tf(xn));
        if (t == 0) out_t[by] = (float)tgt[by];
    } else if (by < B_NUM + CHAIN_BLKS) {   // ---- chain: ballot scans ----
        __shared__ int st[B_NUM];
        #pragma unroll
        for (int k = 0; k < 4; ++k) st[t + k * 256] = tgt[t + k * 256];
        __syncthreads();
        const int lane = t & 31;
        const int i = (by - B_NUM) * 8 + (t >> 5);   // 0..1023, one per warp
        const int me = st[i];
        int prev = -1;
        for (int start = i - 1; start >= 0; start -= 32) {
            int j = start - lane;
            unsigned m = __ballot_sync(0xffffffffu, (j >= 0) && (st[j] == me));
            if (m) { prev = start - (__ffs(m) - 1); break; }
        }
        int nxt = -1;
        for (int start = i + 1; start < B_NUM; start += 32) {
            int j = start + lane;
            unsigned m = __ballot_sync(0xffffffffu, (j < B_NUM) && (st[j] == me));
            if (m) { nxt = start + (__ffs(m) - 1); break; }
        }
        if (lane == 0) {
            g_head[i] = (prev < 0) ? 1 : 0;
            g_next[i] = nxt;
        }
    } else {                             // ---- winv: 2 class rows per warp ----
        int gw = ((by - B_NUM - CHAIN_BLKS) * 8 + (t >> 5)) * 2;
        int lane = t & 31;
        if (gw < C_NUM) {
            const float4* r0 = w4 + (size_t)gw * 64;
            const float4* r1 = w4 + (size_t)(gw + 1) * 64;
            float4 a0 = r0[lane];
            float4 b0 = r0[lane + 32];
            float4 a1 = r1[lane];
            float4 b1 = r1[lane + 32];
            float s0 = a0.x*a0.x + a0.y*a0.y + a0.z*a0.z + a0.w*a0.w
                     + b0.x*b0.x + b0.y*b0.y + b0.z*b0.z + b0.w*b0.w;
            float s1 = a1.x*a1.x + a1.y*a1.y + a1.z*a1.z + a1.w*a1.w
                     + b1.x*b1.x + b1.y*b1.y + b1.z*b1.z + b1.w*b1.w;
            #pragma unroll
            for (int o = 16; o; o >>= 1) {
                s0 += __shfl_xor_sync(0xffffffffu, s0, o);
                s1 += __shfl_xor_sync(0xffffffffu, s1, o);
            }
            if (lane == 0) {
                g_winv[gw] = 1.f / fmaxf(sqrtf(s0), EPSV);
                g_winv[gw + 1] = 1.f / fmaxf(sqrtf(s1), EPSV);
            }
        }
    }
}

// ---------------------------------------------------------------------------
// K_GEMM: TF32 mma.sync. 128x128 CTA tile, 8 warps @ 64x32, BK=32,
//         3-stage cp.async, single barrier/iter, leading copy CTAs,
//         transpose epilogue with coalesced float4 stores.
// ---------------------------------------------------------------------------
#define NSTG 3
#define STG_BYTES 32768            // A(16KB) + B(16KB) per stage
#define OFF_TILE 1024
#define SMEM_BYTES (OFF_TILE + NSTG * STG_BYTES)

__global__ __launch_bounds__(256, 2)
void k_gemm(const float* __restrict__ W, float* __restrict__ out,
            float4* __restrict__ nw4) {
    const int tid = threadIdx.x;

    // ---- leading copy CTAs: W -> new_weight output region (overlaps GEMM) ----
    if (blockIdx.y < COPY_CTAS_Y) {
        const float4* src = (const float4*)W;
        const size_t n4 = (size_t)C_NUM * 64;
        const size_t nthr = (size_t)COPY_CTAS_Y * 8 * 256;   // 32768
        size_t base = (size_t)(blockIdx.y * 8 + blockIdx.x) * 256 + tid;
        size_t i = base;
        for (; i + 3 * nthr < n4; i += 4 * nthr) {
            float4 v0 = src[i];
            float4 v1 = src[i + nthr];
            float4 v2 = src[i + 2 * nthr];
            float4 v3 = src[i + 3 * nthr];
            nw4[i] = v0; nw4[i + nthr] = v1;
            nw4[i + 2 * nthr] = v2; nw4[i + 3 * nthr] = v3;
        }
        for (; i < n4; i += nthr) nw4[i] = src[i];
        return;
    }

    extern __shared__ char smem[];
    const uint32_t sb = smem_u32(smem);
    const int lane = tid & 31, warp = tid >> 5;
    const int b0 = blockIdx.x * 128;                    // batch tile
    const int c0 = (blockIdx.y - COPY_CTAS_Y) * 128;    // class tile
    const int wm = (warp & 1) * 64;
    const int wn = (warp >> 1) * 32;

    float* winv_s = (float*)smem;      // [128] = 30*winv
    if (tid < 128) {
        int c = c0 + tid; if (c >= C_NUM) c = C_NUM - 1;
        winv_s[tid] = 30.0f * g_winv[c];
    }

    const char* Abase = (const char*)g_xnorm + (size_t)b0 * (D_NUM * 4);
    const char* Bbase = (const char*)W;

    auto issue_load = [&](int stage, int chunk) {
        uint32_t abuf = sb + OFF_TILE + stage * STG_BYTES;
        uint32_t bbuf = abuf + 16384;
        #pragma unroll
        for (int i = 0; i < 4; ++i) {
            int slot = tid + i * 256;          // 0..1023
            int r = slot >> 3;
            int sg = (slot & 7) * 16;
            uint32_t so = sw128((uint32_t)(r * 128 + sg));
            cp16(abuf + so, Abase + (size_t)r * 1024 + chunk * 128 + sg);
            int row = c0 + r; if (row >= C_NUM) row = C_NUM - 1;
            cp16(bbuf + so, Bbase + (size_t)row * 1024 + chunk * 128 + sg);
        }
        CP_COMMIT();
    };

    float acc[4][4][4];
    #pragma unroll
    for (int i = 0; i < 4; ++i)
        #pragma unroll
        for (int j = 0; j < 4; ++j)
            #pragma unroll
            for (int r = 0; r < 4; ++r) acc[i][j][r] = 0.f;

    uint32_t a_off[4], b_off[2];
    #pragma unroll
    for (int im = 0; im < 4; ++im)
        a_off[im] = (uint32_t)((wm + im * 16 + (lane & 15)) * 128 + ((lane >> 4) << 4));
    #pragma unroll
    for (int jp = 0; jp < 2; ++jp)
        b_off[jp] = (uint32_t)((wn + jp * 16 + ((lane >> 4) << 3) + (lane & 7)) * 128
                               + (((lane >> 3) & 1) << 4));

    issue_load(0, 0);
    issue_load(1, 1);

    #pragma unroll
    for (int c = 0; c < 8; ++c) {
        if (c < 7) asm volatile("cp.async.wait_group 1;" ::: "memory");
        else       asm volatile("cp.async.wait_group 0;" ::: "memory");
        __syncthreads();
        if (c + 2 < 8) issue_load((c + 2) % NSTG, c + 2);  // stage freed at this barrier

        const uint32_t abuf = sb + OFF_TILE + (c % NSTG) * STG_BYTES;
        const uint32_t bbuf = abuf + 16384;
        #pragma unroll
        for (int ks = 0; ks < 4; ++ks) {
            unsigned af[4][4], bf[2][4];
            #pragma unroll
            for (int im = 0; im < 4; ++im)
                ldsm4(af[im], abuf + sw128(a_off[im] + ks * 32));
            #pragma unroll
            for (int jp = 0; jp < 2; ++jp)
                ldsm4(bf[jp], bbuf + sw128(b_off[jp] + ks * 32));
            #pragma unroll
            for (int im = 0; im < 4; ++im) {
                #pragma unroll
                for (int jp = 0; jp < 2; ++jp) {
                    mma_tf32(acc[im][jp * 2 + 0], af[im], &bf[jp][0]);
                    mma_tf32(acc[im][jp * 2 + 1], af[im], &bf[jp][2]);
                }
            }
        }
    }
    __syncthreads();   // all reads of last stage done before tb reuse

    // epilogue: scale by 30*winv, smem transpose, coalesced float4 stores
    float* tb = (float*)(smem + OFF_TILE);   // [128][132]
    const int g4 = lane >> 2, t4 = lane & 3;
    #pragma unroll
    for (int im = 0; im < 4; ++im) {
        int r = wm + im * 16 + g4;
        #pragma unroll
        for (int jn = 0; jn < 4; ++jn) {
            int col = wn + jn * 8 + t4 * 2;
            float s0 = winv_s[col], s1 = winv_s[col + 1];
            *(float2*)&tb[r * 132 + col] =
                make_float2(acc[im][jn][0] * s0, acc[im][jn][1] * s1);
            *(float2*)&tb[(r + 8) * 132 + col] =
                make_float2(acc[im][jn][2] * s0, acc[im][jn][3] * s1);
        }
    }
    __syncthreads();
    #pragma unroll
    for (int it = 0; it < 16; ++it) {
        int r = warp + it * 8;
        int colb = lane * 4;
        float4 val = *(const float4*)&tb[r * 132 + colb];
        int gc = c0 + colb;
        if (gc < C_NUM)
            *(float4*)&out[(size_t)(b0 + r) * C_NUM + gc] = val;
    }
}

// ---------------------------------------------------------------------------
// K_UPDATE: sequential momentum update per class chain (reads copied rows)
// ---------------------------------------------------------------------------
__global__ void k_update(const int* __restrict__ tgt, float* __restrict__ nw) {
    int b = blockIdx.x;
    if (!g_head[b]) return;
    int t = threadIdx.x;
    int y = tgt[b];
    float v = nw[(size_t)y * D_NUM + t];
    __shared__ float ws[8];
    int cur = b;
    while (cur >= 0) {
        v = 0.5f * v + 0.5f * g_xexact[cur * D_NUM + t];
        float ss = v * v;
        #pragma unroll
        for (int o = 16; o; o >>= 1) ss += __shfl_xor_sync(0xffffffffu, ss, o);
        __syncthreads();
        if ((t & 31) == 0) ws[t >> 5] = ss;
        __syncthreads();
        float tot = 0.f;
        #pragma unroll
        for (int i = 0; i < 8; ++i) tot += ws[i];
        v *= 1.f / fmaxf(sqrtf(tot), EPSV);
        cur = g_next[cur];
    }
    nw[(size_t)y * D_NUM + t] = v;
}

// ---------------------------------------------------------------------------
extern "C" void kernel_launch(void* const* d_in, const int* in_sizes, int n_in,
                              void* d_out, int out_size) {
    const float* x   = (const float*)d_in[0];
    const int*   tgt = (const int*)d_in[1];
    const float* w   = (const float*)d_in[2];
    float* out      = (float*)d_out;
    float* out_pred = out;                                  // [1024][100000]
    float* out_t    = out + (size_t)B_NUM * C_NUM;          // [1024]
    float* out_nw   = out_t + B_NUM;                        // [100000][256]

    static bool attr_set = false;
    if (!attr_set) {
        cudaFuncSetAttribute(k_gemm, cudaFuncAttributeMaxDynamicSharedMemorySize, SMEM_BYTES);
        attr_set = true;
    }

    k_prep<<<B_NUM + CHAIN_BLKS + WINV_BLKS, 256>>>(x, tgt, (const float4*)w, out_t);
    k_gemm<<<dim3(8, COPY_CTAS_Y + GEMM_TILES_Y), 256, SMEM_BYTES>>>(w, out_pred, (float4*)out_nw);
    k_update<<<B_NUM, 256>>>(tgt, out_nw);
}